// round 5
// baseline (speedup 1.0000x reference)
#include <cuda_runtime.h>

// Policy_5480378269890 — NAF policy head, batch=2. Single block, 512 threads.
// Latency-bound. Key discipline: every global load is issued in a batch with
// its consumer far away (one scoreboard wait per batch), never load->use->load.
// Prologue (conv/linear/BN) runs on warps 14-15 entirely out of registers.
//
// Inputs: 0 inputs[2,32] 1 u[2,8]
//  2..13 branch params (w*c[16,2,4] b*c[16] w*o[16,48] b*o[16]) x3
//  14 g0[32] 15 be0[32] 16 W1[128,32] 17 bl1[128] 18 W2[128,128] 19 bl2[128]
//  20 Vw[1,128] 21 Vb[1] 22 Mw[8,128] 23 Mb[8] 24 Lw[64,128] 25 Lb[64]
// Output: mu[16] | Q[2] | V[2]

struct Params {
    const float* p[26];
    float* out;
};

__device__ __forceinline__ float4 ldg4v(const float* p) {
    float4 r;
    asm volatile("ld.global.nc.v4.f32 {%0,%1,%2,%3}, [%4];"
                 : "=f"(r.x), "=f"(r.y), "=f"(r.z), "=f"(r.w) : "l"(p));
    return r;
}
__device__ __forceinline__ float ldgv(const float* p) {
    float r;
    asm volatile("ld.global.nc.f32 %0, [%1];" : "=f"(r) : "l"(p));
    return r;
}

__device__ __forceinline__ float dot4(float4 a, float4 b) {
    return a.x * b.x + a.y * b.y + a.z * b.z + a.w * b.w;
}

// Fast tanh: 1 - 2/(exp(2x)+1). abs err ~1e-6, robust at +-inf.
__device__ __forceinline__ float ftanh(float x) {
    float e = __expf(2.0f * x);
    return 1.0f - __fdividef(2.0f, e + 1.0f);
}

// Butterfly-reduce 8 independent per-lane partials (outputs g=0..7) across the
// warp, two batches at once. After return lane group g=(lane>>2) holds the
// total for output g; lanes with (lane&3)==0 are canonical writers.
__device__ __forceinline__ float2 bfly8x2(const float p0[8], const float p1[8], int lane) {
    const bool b4 = (lane & 16) != 0;
    const bool b3 = (lane & 8) != 0;
    const bool b2 = (lane & 4) != 0;
    float q0[4], q1[4];
    #pragma unroll
    for (int i = 0; i < 4; i++) {
        float k0 = b4 ? p0[i + 4] : p0[i];
        float s0 = b4 ? p0[i]     : p0[i + 4];
        float k1 = b4 ? p1[i + 4] : p1[i];
        float s1 = b4 ? p1[i]     : p1[i + 4];
        q0[i] = k0 + __shfl_xor_sync(0xffffffffu, s0, 16);
        q1[i] = k1 + __shfl_xor_sync(0xffffffffu, s1, 16);
    }
    float r0[2], r1[2];
    #pragma unroll
    for (int i = 0; i < 2; i++) {
        float k0 = b3 ? q0[i + 2] : q0[i];
        float s0 = b3 ? q0[i]     : q0[i + 2];
        float k1 = b3 ? q1[i + 2] : q1[i];
        float s1 = b3 ? q1[i]     : q1[i + 2];
        r0[i] = k0 + __shfl_xor_sync(0xffffffffu, s0, 8);
        r1[i] = k1 + __shfl_xor_sync(0xffffffffu, s1, 8);
    }
    float k0 = b2 ? r0[1] : r0[0];
    float s0 = b2 ? r0[0] : r0[1];
    float k1 = b2 ? r1[1] : r1[0];
    float s1 = b2 ? r1[0] : r1[1];
    float t0 = k0 + __shfl_xor_sync(0xffffffffu, s0, 4);
    float t1 = k1 + __shfl_xor_sync(0xffffffffu, s1, 4);
    t0 += __shfl_xor_sync(0xffffffffu, t0, 2);
    t1 += __shfl_xor_sync(0xffffffffu, t1, 2);
    t0 += __shfl_xor_sync(0xffffffffu, t0, 1);
    t1 += __shfl_xor_sync(0xffffffffu, t1, 1);
    return make_float2(t0, t1);
}

__global__ void __launch_bounds__(512, 1) policy_kernel(Params P) {
    __shared__ __align__(16) float pooled[3][48];
    __shared__ float xcat[2][32];
    __shared__ float xbn[2][32];
    __shared__ __align__(16) float h1[2][128];
    __shared__ __align__(16) float h2[2][128];
    __shared__ float Lsm[2][64];
    __shared__ float musm[2][8];
    __shared__ float Vsm[2];
    __shared__ float usm[16];

    const int t    = threadIdx.x;
    const int warp = t >> 5;
    const int lane = t & 31;
    const int g    = lane >> 2;
    const bool writer = (lane & 3) == 0;

    float  w1r[8];
    float4 w2r[8];
    float4 whr[8];
    float  hb = 0.0f, b1r, b2r;

    if (warp >= 14) {
        // ====== prologue warps 14-15: BATCHED register staging ============
        const int lt = t - 448;             // 0..63
        const bool isconv = lt < 48;
        const int br = isconv ? (lt / 16) : 0;
        const int o  = isconv ? (lt % 16) : 0;
        const float* inputs = P.p[0];

        // -- one burst of loads, consumers all far below --
        float4 ia, ib, ic, id, wca, wcb;
        float  bc_v = 0.f, bo_v = 0.f;
        float4 wo_v[12];
        if (isconv) {
            ia  = ldg4v(inputs + br * 8);
            ib  = ldg4v(inputs + br * 8 + 4);
            ic  = ldg4v(inputs + 32 + br * 8);
            id  = ldg4v(inputs + 32 + br * 8 + 4);
            wca = ldg4v(P.p[2 + br * 4] + o * 8);
            wcb = ldg4v(P.p[2 + br * 4] + o * 8 + 4);
            bc_v = ldgv(P.p[3 + br * 4] + o);
            bo_v = ldgv(P.p[5 + br * 4] + o);
            #pragma unroll
            for (int i = 0; i < 12; i++)
                wo_v[i] = ldg4v(P.p[4 + br * 4] + o * 48 + i * 4);
        }
        float pv = 0.f, u_v = 0.f;
        if (lt >= 48) {
            int idx = lt - 48;
            pv  = ldgv(inputs + (idx >> 3) * 32 + 24 + (idx & 7));
            u_v = ldgv(P.p[1] + idx);
        }
        float g_v = 0.f, be_v = 0.f;
        if (warp == 14) { g_v = ldgv(P.p[14] + lane); be_v = ldgv(P.p[15] + lane); }
        #pragma unroll
        for (int i = 0; i < 8; i++)
            w1r[i] = ldgv(P.p[16] + (warp * 8 + i) * 32 + lane);
        b1r = ldgv(P.p[17] + warp * 8 + g);
        b2r = ldgv(P.p[19] + warp * 8 + g);

        // -- Phase 1a: conv1d(2->16,k4,p1) + relu + maxpool2 (registers) --
        if (isconv) {
            float xin[2][8] = {{ia.x, ia.y, ia.z, ia.w, ib.x, ib.y, ib.z, ib.w},
                               {ic.x, ic.y, ic.z, ic.w, id.x, id.y, id.z, id.w}};
            float wc[2][4]  = {{wca.x, wca.y, wca.z, wca.w},
                               {wcb.x, wcb.y, wcb.z, wcb.w}};
            float y[7];
            #pragma unroll
            for (int tt = 0; tt < 7; tt++) {
                float acc = bc_v;
                #pragma unroll
                for (int i = 0; i < 2; i++) {
                    #pragma unroll
                    for (int k = 0; k < 4; k++) {
                        int j = tt - 1 + k;
                        if (j >= 0 && j < 8)
                            acc += xin[i][j] * wc[i][k];
                    }
                }
                y[tt] = fmaxf(acc, 0.0f);
            }
            #pragma unroll
            for (int s = 0; s < 3; s++)
                pooled[br][o * 3 + s] = fmaxf(y[2 * s], y[2 * s + 1]);
        } else {
            int idx = lt - 48;
            xcat[idx >> 3][24 + (idx & 7)] = pv;
            usm[idx] = u_v;
        }
        asm volatile("bar.sync 1, 64;" ::: "memory");

        // -- Phase 1b: Linear(48,16) from registers + pooled smem ----------
        if (isconv) {
            const float4* p4 = reinterpret_cast<const float4*>(&pooled[br][0]);
            float accA = bo_v, accB = 0.0f;
            #pragma unroll
            for (int q = 0; q < 12; q += 2) {
                accA += dot4(wo_v[q],     p4[q]);
                accB += dot4(wo_v[q + 1], p4[q + 1]);
            }
            xcat[o >> 3][br * 8 + (o & 7)] = accA + accB;
        }
        asm volatile("bar.sync 1, 64;" ::: "memory");

        // -- Phase 2: BatchNorm1d (train, batch=2), warp 14 ----------------
        if (warp == 14) {
            float x0 = xcat[0][lane], x1 = xcat[1][lane];
            float m  = 0.5f * (x0 + x1);
            float d0 = x0 - m, d1 = x1 - m;
            float v  = 0.5f * (d0 * d0 + d1 * d1);
            float inv = rsqrtf(v + 1e-5f);
            xbn[0][lane] = g_v * d0 * inv + be_v;
            xbn[1][lane] = g_v * d1 * inv + be_v;
        }

        // -- w2r prefetch (needed only in phase 4, ~300+ cyc away) --------
        #pragma unroll
        for (int i = 0; i < 8; i++)
            w2r[i] = ldg4v(P.p[18] + (warp * 8 + i) * 128 + lane * 4);
    } else {
        // ====== compute warps 0-13: register weight prefetch ==============
        #pragma unroll
        for (int i = 0; i < 8; i++)
            w1r[i] = ldgv(P.p[16] + (warp * 8 + i) * 32 + lane);
        #pragma unroll
        for (int i = 0; i < 8; i++)
            w2r[i] = ldg4v(P.p[18] + (warp * 8 + i) * 128 + lane * 4);
        if (warp < 8) {                         // L head rows warp*8..+7
            #pragma unroll
            for (int i = 0; i < 8; i++)
                whr[i] = ldg4v(P.p[24] + (warp * 8 + i) * 128 + lane * 4);
            hb = ldgv(P.p[25] + warp * 8 + g);
        } else if (warp == 8) {                 // mu head
            #pragma unroll
            for (int i = 0; i < 8; i++)
                whr[i] = ldg4v(P.p[22] + i * 128 + lane * 4);
            hb = ldgv(P.p[23] + g);
        } else if (warp == 9) {                 // V head
            whr[0] = ldg4v(P.p[20] + lane * 4);
            hb = ldgv(P.p[21]);
        }
        b1r = ldgv(P.p[17] + warp * 8 + g);
        b2r = ldgv(P.p[19] + warp * 8 + g);
    }
    __syncthreads();

    // ================= Phase 3: h1 = tanh(xbn @ W1^T + bl1) ===============
    {
        float x0 = xbn[0][lane], x1 = xbn[1][lane];
        float p0[8], p1[8];
        #pragma unroll
        for (int i = 0; i < 8; i++) { p0[i] = w1r[i] * x0; p1[i] = w1r[i] * x1; }
        float2 r = bfly8x2(p0, p1, lane);
        if (writer) {
            int o = warp * 8 + g;
            h1[0][o] = ftanh(r.x + b1r);
            h1[1][o] = ftanh(r.y + b1r);
        }
    }
    __syncthreads();

    // ================= Phase 4: h2 = tanh(h1 @ W2^T + bl2) ================
    {
        float4 v0 = reinterpret_cast<const float4*>(&h1[0][0])[lane];
        float4 v1 = reinterpret_cast<const float4*>(&h1[1][0])[lane];
        float p0[8], p1[8];
        #pragma unroll
        for (int i = 0; i < 8; i++) { p0[i] = dot4(w2r[i], v0); p1[i] = dot4(w2r[i], v1); }
        float2 r = bfly8x2(p0, p1, lane);
        if (writer) {
            int o = warp * 8 + g;
            h2[0][o] = ftanh(r.x + b2r);
            h2[1][o] = ftanh(r.y + b2r);
        }
    }
    __syncthreads();

    // ================= Phase 5: heads (L: warps 0-7, mu: 8, V: 9) =========
    {
        float4 v0 = reinterpret_cast<const float4*>(&h2[0][0])[lane];
        float4 v1 = reinterpret_cast<const float4*>(&h2[1][0])[lane];
        if (warp < 8) {
            float p0[8], p1[8];
            #pragma unroll
            for (int i = 0; i < 8; i++) { p0[i] = dot4(whr[i], v0); p1[i] = dot4(whr[i], v1); }
            float2 r = bfly8x2(p0, p1, lane);
            if (writer) {
                int o = warp * 8 + g;
                int ii = o >> 3, jj = o & 7;
                float pa = r.x + hb, pb = r.y + hb;
                Lsm[0][o] = (ii > jj) ? pa : ((ii == jj) ? __expf(pa) : 0.0f);
                Lsm[1][o] = (ii > jj) ? pb : ((ii == jj) ? __expf(pb) : 0.0f);
            }
        } else if (warp == 8) {
            float p0[8], p1[8];
            #pragma unroll
            for (int i = 0; i < 8; i++) { p0[i] = dot4(whr[i], v0); p1[i] = dot4(whr[i], v1); }
            float2 r = bfly8x2(p0, p1, lane);
            if (writer) {
                musm[0][g] = ftanh(r.x + hb);
                musm[1][g] = ftanh(r.y + hb);
            }
        } else if (warp == 9) {
            float a0 = dot4(whr[0], v0);
            float a1 = dot4(whr[0], v1);
            #pragma unroll
            for (int off = 16; off > 0; off >>= 1) {
                a0 += __shfl_xor_sync(0xffffffffu, a0, off);
                a1 += __shfl_xor_sync(0xffffffffu, a1, off);
            }
            if (lane == 0) { Vsm[0] = a0 + hb; Vsm[1] = a1 + hb; }
        }
    }
    __syncthreads();

    // ================= Phase 6: advantage + outputs (warp 0) ==============
    if (warp == 0) {
        int ln = lane & 15;
        int b = ln >> 3, j = ln & 7;
        float d[8];
        #pragma unroll
        for (int i = 0; i < 8; i++) d[i] = usm[b * 8 + i] - musm[b][i];
        float y = 0.0f;
        #pragma unroll
        for (int i = 0; i < 8; i++)
            if (i >= j) y += d[i] * Lsm[b][i * 8 + j];
        float acc = y * y;
        acc += __shfl_xor_sync(0xffffffffu, acc, 1);
        acc += __shfl_xor_sync(0xffffffffu, acc, 2);
        acc += __shfl_xor_sync(0xffffffffu, acc, 4);
        if (lane < 16) {
            P.out[lane] = musm[b][j];                       // mu
            if (j == 0) {
                P.out[16 + b] = -0.5f * acc + Vsm[b];       // Q
                P.out[18 + b] = Vsm[b];                     // V
            }
        }
    }
}

extern "C" void kernel_launch(void* const* d_in, const int* in_sizes, int n_in,
                              void* d_out, int out_size) {
    (void)in_sizes; (void)n_in; (void)out_size;
    Params P;
    #pragma unroll
    for (int i = 0; i < 26; i++) P.p[i] = (const float*)d_in[i];
    P.out = (float*)d_out;
    policy_kernel<<<1, 512>>>(P);
}

// round 6
// speedup vs baseline: 1.3413x; 1.3413x over previous
#include <cuda_runtime.h>

// Policy_5480378269890 — NAF policy head, batch=2. Single block, 512 threads.
// Latency-bound. One batched global-load burst per warp (single scoreboard
// wait); prologue on warps 14-15 entirely in registers; butterfly 8-output
// warp reductions; L head trimmed to the 36 lower-triangle rows (upper rows
// are multiplied by 0 in the reference and never observed).
//
// Inputs: 0 inputs[2,32] 1 u[2,8]
//  2..13 branch params (w*c[16,2,4] b*c[16] w*o[16,48] b*o[16]) x3
//  14 g0[32] 15 be0[32] 16 W1[128,32] 17 bl1[128] 18 W2[128,128] 19 bl2[128]
//  20 Vw[1,128] 21 Vb[1] 22 Mw[8,128] 23 Mb[8] 24 Lw[64,128] 25 Lb[64]
// Output: mu[16] | Q[2] | V[2]

struct Params {
    const float* p[26];
    float* out;
};

// 36 lower-triangle row indices (i*8+j, i>=j), padded to 40 (8 per warp x 5).
__constant__ unsigned char LROW[40] = {
    0,  8, 9, 16, 17, 18, 24, 25,
    26, 27, 32, 33, 34, 35, 36, 40,
    41, 42, 43, 44, 45, 48, 49, 50,
    51, 52, 53, 54, 56, 57, 58, 59,
    60, 61, 62, 63, 0, 0, 0, 0
};

__device__ __forceinline__ float4 ldg4v(const float* p) {
    float4 r;
    asm volatile("ld.global.nc.v4.f32 {%0,%1,%2,%3}, [%4];"
                 : "=f"(r.x), "=f"(r.y), "=f"(r.z), "=f"(r.w) : "l"(p));
    return r;
}
__device__ __forceinline__ float ldgv(const float* p) {
    float r;
    asm volatile("ld.global.nc.f32 %0, [%1];" : "=f"(r) : "l"(p));
    return r;
}

__device__ __forceinline__ float dot4(float4 a, float4 b) {
    return a.x * b.x + a.y * b.y + a.z * b.z + a.w * b.w;
}

// Fast tanh: 1 - 2/(exp(2x)+1). abs err ~1e-6, robust at +-inf.
__device__ __forceinline__ float ftanh(float x) {
    float e = __expf(2.0f * x);
    return 1.0f - __fdividef(2.0f, e + 1.0f);
}

// Butterfly-reduce 8 independent per-lane partials (outputs g=0..7) across the
// warp, two batches at once. Lane group g=(lane>>2) ends with output g's
// total; lanes with (lane&3)==0 are canonical writers.
__device__ __forceinline__ float2 bfly8x2(const float p0[8], const float p1[8], int lane) {
    const bool b4 = (lane & 16) != 0;
    const bool b3 = (lane & 8) != 0;
    const bool b2 = (lane & 4) != 0;
    float q0[4], q1[4];
    #pragma unroll
    for (int i = 0; i < 4; i++) {
        float k0 = b4 ? p0[i + 4] : p0[i];
        float s0 = b4 ? p0[i]     : p0[i + 4];
        float k1 = b4 ? p1[i + 4] : p1[i];
        float s1 = b4 ? p1[i]     : p1[i + 4];
        q0[i] = k0 + __shfl_xor_sync(0xffffffffu, s0, 16);
        q1[i] = k1 + __shfl_xor_sync(0xffffffffu, s1, 16);
    }
    float r0[2], r1[2];
    #pragma unroll
    for (int i = 0; i < 2; i++) {
        float k0 = b3 ? q0[i + 2] : q0[i];
        float s0 = b3 ? q0[i]     : q0[i + 2];
        float k1 = b3 ? q1[i + 2] : q1[i];
        float s1 = b3 ? q1[i]     : q1[i + 2];
        r0[i] = k0 + __shfl_xor_sync(0xffffffffu, s0, 8);
        r1[i] = k1 + __shfl_xor_sync(0xffffffffu, s1, 8);
    }
    float k0 = b2 ? r0[1] : r0[0];
    float s0 = b2 ? r0[0] : r0[1];
    float k1 = b2 ? r1[1] : r1[0];
    float s1 = b2 ? r1[0] : r1[1];
    float t0 = k0 + __shfl_xor_sync(0xffffffffu, s0, 4);
    float t1 = k1 + __shfl_xor_sync(0xffffffffu, s1, 4);
    t0 += __shfl_xor_sync(0xffffffffu, t0, 2);
    t1 += __shfl_xor_sync(0xffffffffu, t1, 2);
    t0 += __shfl_xor_sync(0xffffffffu, t0, 1);
    t1 += __shfl_xor_sync(0xffffffffu, t1, 1);
    return make_float2(t0, t1);
}

__global__ void __launch_bounds__(512, 1) policy_kernel(Params P) {
    __shared__ __align__(16) float pooled[3][48];
    __shared__ float xcat[2][32];
    __shared__ float xbn[2][32];
    __shared__ __align__(16) float h1[2][128];
    __shared__ __align__(16) float h2[2][128];
    __shared__ float Lsm[2][64];
    __shared__ float musm[2][8];
    __shared__ float Vsm[2];
    __shared__ float usm[16];

    const int t    = threadIdx.x;
    const int warp = t >> 5;
    const int lane = t & 31;
    const int g    = lane >> 2;
    const bool writer = (lane & 3) == 0;

    float  w1r[8];
    float4 w2r[8];
    float4 whr[8];
    float  hb = 0.0f, b1r, b2r;
    int    myrow = 0;

    if (warp >= 14) {
        // ====== prologue warps 14-15: BATCHED register staging ============
        const int lt = t - 448;             // 0..63
        const bool isconv = lt < 48;
        const int br = isconv ? (lt / 16) : 0;
        const int o  = isconv ? (lt % 16) : 0;
        const float* inputs = P.p[0];

        // -- one burst of loads, consumers all far below --
        float4 ia, ib, ic, id, wca, wcb;
        float  bc_v = 0.f, bo_v = 0.f;
        float4 wo_v[12];
        if (isconv) {
            ia  = ldg4v(inputs + br * 8);
            ib  = ldg4v(inputs + br * 8 + 4);
            ic  = ldg4v(inputs + 32 + br * 8);
            id  = ldg4v(inputs + 32 + br * 8 + 4);
            wca = ldg4v(P.p[2 + br * 4] + o * 8);
            wcb = ldg4v(P.p[2 + br * 4] + o * 8 + 4);
            bc_v = ldgv(P.p[3 + br * 4] + o);
            bo_v = ldgv(P.p[5 + br * 4] + o);
            #pragma unroll
            for (int i = 0; i < 12; i++)
                wo_v[i] = ldg4v(P.p[4 + br * 4] + o * 48 + i * 4);
        }
        float pv = 0.f, u_v = 0.f;
        if (lt >= 48) {
            int idx = lt - 48;
            pv  = ldgv(inputs + (idx >> 3) * 32 + 24 + (idx & 7));
            u_v = ldgv(P.p[1] + idx);
        }
        float g_v = 0.f, be_v = 0.f;
        if (warp == 14) { g_v = ldgv(P.p[14] + lane); be_v = ldgv(P.p[15] + lane); }
        #pragma unroll
        for (int i = 0; i < 8; i++)
            w1r[i] = ldgv(P.p[16] + (warp * 8 + i) * 32 + lane);
        b1r = ldgv(P.p[17] + warp * 8 + g);
        b2r = ldgv(P.p[19] + warp * 8 + g);

        // -- Phase 1a: conv1d(2->16,k4,p1) + relu + maxpool2 (registers) --
        if (isconv) {
            float xin[2][8] = {{ia.x, ia.y, ia.z, ia.w, ib.x, ib.y, ib.z, ib.w},
                               {ic.x, ic.y, ic.z, ic.w, id.x, id.y, id.z, id.w}};
            float wc[2][4]  = {{wca.x, wca.y, wca.z, wca.w},
                               {wcb.x, wcb.y, wcb.z, wcb.w}};
            float y[7];
            #pragma unroll
            for (int tt = 0; tt < 7; tt++) {
                float acc = bc_v;
                #pragma unroll
                for (int i = 0; i < 2; i++) {
                    #pragma unroll
                    for (int k = 0; k < 4; k++) {
                        int j = tt - 1 + k;
                        if (j >= 0 && j < 8)
                            acc += xin[i][j] * wc[i][k];
                    }
                }
                y[tt] = fmaxf(acc, 0.0f);
            }
            #pragma unroll
            for (int s = 0; s < 3; s++)
                pooled[br][o * 3 + s] = fmaxf(y[2 * s], y[2 * s + 1]);
        } else {
            int idx = lt - 48;
            xcat[idx >> 3][24 + (idx & 7)] = pv;
            usm[idx] = u_v;
        }
        asm volatile("bar.sync 1, 64;" ::: "memory");

        // -- Phase 1b: Linear(48,16) from registers + pooled smem ----------
        if (isconv) {
            const float4* p4 = reinterpret_cast<const float4*>(&pooled[br][0]);
            float accA = bo_v, accB = 0.0f;
            #pragma unroll
            for (int q = 0; q < 12; q += 2) {
                accA += dot4(wo_v[q],     p4[q]);
                accB += dot4(wo_v[q + 1], p4[q + 1]);
            }
            xcat[o >> 3][br * 8 + (o & 7)] = accA + accB;
        }
        asm volatile("bar.sync 1, 64;" ::: "memory");

        // -- Phase 2: BatchNorm1d (train, batch=2), warp 14 ----------------
        if (warp == 14) {
            float x0 = xcat[0][lane], x1 = xcat[1][lane];
            float m  = 0.5f * (x0 + x1);
            float d0 = x0 - m, d1 = x1 - m;
            float v  = 0.5f * (d0 * d0 + d1 * d1);
            float inv = rsqrtf(v + 1e-5f);
            xbn[0][lane] = g_v * d0 * inv + be_v;
            xbn[1][lane] = g_v * d1 * inv + be_v;
        }

        // -- w2r prefetch (needed only in phase 4, far away) ---------------
        #pragma unroll
        for (int i = 0; i < 8; i++)
            w2r[i] = ldg4v(P.p[18] + (warp * 8 + i) * 128 + lane * 4);
    } else {
        // ====== compute warps 0-13: register weight prefetch ==============
        #pragma unroll
        for (int i = 0; i < 8; i++)
            w1r[i] = __ldg(P.p[16] + (warp * 8 + i) * 32 + lane);
        #pragma unroll
        for (int i = 0; i < 8; i++)
            w2r[i] = __ldg(reinterpret_cast<const float4*>(P.p[18] + (warp * 8 + i) * 128) + lane);
        if (warp < 5) {                         // L head: 36 tri rows, 8 tasks/warp
            myrow = LROW[warp * 8 + g];
            #pragma unroll
            for (int i = 0; i < 8; i++) {
                int row = LROW[warp * 8 + i];
                whr[i] = __ldg(reinterpret_cast<const float4*>(P.p[24] + row * 128) + lane);
            }
            hb = __ldg(P.p[25] + myrow);
        } else if (warp == 5) {                 // mu head
            #pragma unroll
            for (int i = 0; i < 8; i++)
                whr[i] = __ldg(reinterpret_cast<const float4*>(P.p[22] + i * 128) + lane);
            hb = __ldg(P.p[23] + g);
        } else if (warp == 6) {                 // V head
            whr[0] = __ldg(reinterpret_cast<const float4*>(P.p[20]) + lane);
            hb = __ldg(P.p[21]);
        }
        b1r = __ldg(P.p[17] + warp * 8 + g);
        b2r = __ldg(P.p[19] + warp * 8 + g);
    }
    __syncthreads();

    // ================= Phase 3: h1 = tanh(xbn @ W1^T + bl1) ===============
    {
        float x0 = xbn[0][lane], x1 = xbn[1][lane];
        float p0[8], p1[8];
        #pragma unroll
        for (int i = 0; i < 8; i++) { p0[i] = w1r[i] * x0; p1[i] = w1r[i] * x1; }
        float2 r = bfly8x2(p0, p1, lane);
        if (writer) {
            int o = warp * 8 + g;
            h1[0][o] = ftanh(r.x + b1r);
            h1[1][o] = ftanh(r.y + b1r);
        }
    }
    __syncthreads();

    // ================= Phase 4: h2 = tanh(h1 @ W2^T + bl2) ================
    {
        float4 v0 = reinterpret_cast<const float4*>(&h1[0][0])[lane];
        float4 v1 = reinterpret_cast<const float4*>(&h1[1][0])[lane];
        float p0[8], p1[8];
        #pragma unroll
        for (int i = 0; i < 8; i++) { p0[i] = dot4(w2r[i], v0); p1[i] = dot4(w2r[i], v1); }
        float2 r = bfly8x2(p0, p1, lane);
        if (writer) {
            int o = warp * 8 + g;
            h2[0][o] = ftanh(r.x + b2r);
            h2[1][o] = ftanh(r.y + b2r);
        }
    }
    __syncthreads();

    // ===== Phase 5: heads (L tri rows: warps 0-4, mu: 5, V: 6) ============
    {
        float4 v0 = reinterpret_cast<const float4*>(&h2[0][0])[lane];
        float4 v1 = reinterpret_cast<const float4*>(&h2[1][0])[lane];
        if (warp < 5) {
            float p0[8], p1[8];
            #pragma unroll
            for (int i = 0; i < 8; i++) { p0[i] = dot4(whr[i], v0); p1[i] = dot4(whr[i], v1); }
            float2 r = bfly8x2(p0, p1, lane);
            int task = warp * 8 + g;
            if (writer && task < 36) {
                int ii = myrow >> 3, jj = myrow & 7;
                float pa = r.x + hb, pb = r.y + hb;
                Lsm[0][myrow] = (ii == jj) ? __expf(pa) : pa;
                Lsm[1][myrow] = (ii == jj) ? __expf(pb) : pb;
            }
        } else if (warp == 5) {
            float p0[8], p1[8];
            #pragma unroll
            for (int i = 0; i < 8; i++) { p0[i] = dot4(whr[i], v0); p1[i] = dot4(whr[i], v1); }
            float2 r = bfly8x2(p0, p1, lane);
            if (writer) {
                musm[0][g] = ftanh(r.x + hb);
                musm[1][g] = ftanh(r.y + hb);
            }
        } else if (warp == 6) {
            float a0 = dot4(whr[0], v0);
            float a1 = dot4(whr[0], v1);
            #pragma unroll
            for (int off = 16; off > 0; off >>= 1) {
                a0 += __shfl_xor_sync(0xffffffffu, a0, off);
                a1 += __shfl_xor_sync(0xffffffffu, a1, off);
            }
            if (lane == 0) { Vsm[0] = a0 + hb; Vsm[1] = a1 + hb; }
        }
    }
    __syncthreads();

    // ================= Phase 6: advantage + outputs (warp 0) ==============
    if (warp == 0) {
        int ln = lane & 15;
        int b = ln >> 3, j = ln & 7;
        float d[8];
        #pragma unroll
        for (int i = 0; i < 8; i++) d[i] = usm[b * 8 + i] - musm[b][i];
        float y = 0.0f;
        #pragma unroll
        for (int i = 0; i < 8; i++)
            if (i >= j) y += d[i] * Lsm[b][i * 8 + j];   // only tri entries read
        float acc = y * y;
        acc += __shfl_xor_sync(0xffffffffu, acc, 1);
        acc += __shfl_xor_sync(0xffffffffu, acc, 2);
        acc += __shfl_xor_sync(0xffffffffu, acc, 4);
        if (lane < 16) {
            P.out[lane] = musm[b][j];                       // mu
            if (j == 0) {
                P.out[16 + b] = -0.5f * acc + Vsm[b];       // Q
                P.out[18 + b] = Vsm[b];                     // V
            }
        }
    }
}

extern "C" void kernel_launch(void* const* d_in, const int* in_sizes, int n_in,
                              void* d_out, int out_size) {
    (void)in_sizes; (void)n_in; (void)out_size;
    Params P;
    #pragma unroll
    for (int i = 0; i < 26; i++) P.p[i] = (const float*)d_in[i];
    P.out = (float*)d_out;
    policy_kernel<<<1, 512>>>(P);
}